// round 1
// baseline (speedup 1.0000x reference)
#include <cuda_runtime.h>
#include <cstdint>

// Problem constants
#define NB       128
#define C_DIM    64
#define HW_DIM   3136
#define M_DIM    6
#define D_DIM    192
#define INNER    512
#define NROWS    48      // heads*M
#define TN       64      // n-tile
#define NT       49      // HW/TN (exact)
#define NTHREADS 256

typedef unsigned long long u64;

// ---- packed f32x2 helpers (sm_100+) ----
__device__ __forceinline__ u64 ffma2(u64 a, u64 b, u64 c){
    u64 d; asm("fma.rn.f32x2 %0, %1, %2, %3;" : "=l"(d) : "l"(a), "l"(b), "l"(c)); return d;
}
__device__ __forceinline__ u64 fadd2(u64 a, u64 b){
    u64 d; asm("add.rn.f32x2 %0, %1, %2;" : "=l"(d) : "l"(a), "l"(b)); return d;
}
__device__ __forceinline__ u64 pack2(float x, float y){
    u64 d; asm("mov.b64 %0, {%1, %2};" : "=l"(d) : "f"(x), "f"(y)); return d;
}
__device__ __forceinline__ float2 unpack2(u64 a){
    float2 f; asm("mov.b64 {%0, %1}, %2;" : "=f"(f.x), "=f"(f.y) : "l"(a)); return f;
}

// shared memory layout (float offsets). q2/p2 rows padded to 66 u64 to kill
// cross-ty-group bank aliasing; xnc uses an XOR-4 swizzle at stride 64.
#define Q2_OFF    0                       // u64 [48][66]  = 6336 floats
#define XCN_OFF   6336                    // float [2][64][64]
#define XNC_OFF   (6336 + 8192)           // float [2][64][64] (swizzled)
#define P2_OFF    (6336 + 8192 + 8192)    // u64 [48][66]  = 6336 floats
#define SMEM_FLOATS (6336 + 8192 + 8192 + 6336)   // 29056 floats = 116224 B

__global__ void __launch_bounds__(NTHREADS, 1)
m2f_kernel(const float* __restrict__ x, const float* __restrict__ z,
           const float* __restrict__ Wq, const float* __restrict__ bq,
           const float* __restrict__ Wo, const float* __restrict__ bo,
           float* __restrict__ out)
{
    extern __shared__ float sm[];
    u64*   q2  = (u64*)sm;                 // [48][66] duplicated-pair scaled q
    float* xcn = sm + XCN_OFF;             // c-major x tile, double buffered
    float* xnc = sm + XNC_OFF;             // n-major x tile (swizzled), double buffered
    u64*   p2  = (u64*)(sm + P2_OFF);      // [48][66] duplicated-pair exp(S)

    const int b   = blockIdx.x;
    const int tid = threadIdx.x;
    const int ty  = tid >> 4;              // 0..15
    const int tx  = tid & 15;              // 0..15
    const int r0  = ty * 3;                // 3 rows per thread (48 rows)
    const int c0  = tx * 4;                // 4 cols per thread (64 cols)

    // ---------------- stage z (into xcn area, freed before tiles) ----------------
    float* zs = xcn;
    {
        const float* zb = z + (size_t)b * (M_DIM * D_DIM);
        for (int i = tid; i < M_DIM * D_DIM; i += NTHREADS) zs[i] = zb[i];
    }
    __syncthreads();

    // ---------------- q projection: qflat[3072] = z[b] @ Wq + bq, * C^-0.5 ------
    {
        const int j0 = tid * 2;            // 256 threads x 2 cols = 512
        float ax[M_DIM], ay[M_DIM];
        const float b0 = bq[j0], b1 = bq[j0 + 1];
        #pragma unroll
        for (int m = 0; m < M_DIM; m++){ ax[m] = b0; ay[m] = b1; }
        #pragma unroll 4
        for (int k = 0; k < D_DIM; k++){
            float2 w = *(const float2*)(Wq + (size_t)k * INNER + j0);
            #pragma unroll
            for (int m = 0; m < M_DIM; m++){
                float zv = zs[m * D_DIM + k];
                ax[m] = fmaf(zv, w.x, ax[m]);
                ay[m] = fmaf(zv, w.y, ay[m]);
            }
        }
        const float scale = 0.125f;        // 64^-0.5 folded into q
        #pragma unroll
        for (int m = 0; m < M_DIM; m++){
            int f0 = m * INNER + j0;       // flat [6,512] == flat [48,64]
            int r_ = f0 >> 6, c_ = f0 & 63;
            float qa = ax[m] * scale, qb = ay[m] * scale;
            q2[r_ * 66 + c_]     = pack2(qa, qa);
            q2[r_ * 66 + c_ + 1] = pack2(qb, qb);
        }
    }
    __syncthreads();   // q2 ready; zs dead -> xcn reusable

    // ---------------- main fused attention loop --------------------------------
    const float* xb = x + (size_t)b * C_DIM * HW_DIM;
    float4 pref[4];

    // prefetch tile 0 (slot s = tid + 256p -> c = s>>4, n-group g = s&15)
    #pragma unroll
    for (int p = 0; p < 4; p++){
        int s = tid + NTHREADS * p;
        int cc = s >> 4, g = s & 15;
        pref[p] = *(const float4*)(xb + (size_t)cc * HW_DIM + 4 * g);
    }

    auto store_tile = [&](int buf){
        float* xc = xcn + buf * (C_DIM * TN);
        float* xn = xnc + buf * (TN * C_DIM);
        #pragma unroll
        for (int p = 0; p < 4; p++){
            int s = tid + NTHREADS * p;
            int cc = s >> 4, g = s & 15;
            *(float4*)(xc + cc * TN + 4 * g) = pref[p];
            float v[4] = {pref[p].x, pref[p].y, pref[p].z, pref[p].w};
            #pragma unroll
            for (int kk = 0; kk < 4; kk++){
                int n = 4 * g + kk;
                int csw = ((cc & ~3) ^ ((n & 15) << 2)) | (cc & 3);  // XOR-4 swizzle
                xn[n * 64 + csw] = v[kk];
            }
        }
    };

    u64 oacc[3][2], rsum[3];
    #pragma unroll
    for (int i = 0; i < 3; i++){ oacc[i][0] = 0ULL; oacc[i][1] = 0ULL; rsum[i] = 0ULL; }

    store_tile(0);
    __syncthreads();

    const u64* q2r = q2 + r0 * 66;
    u64*       p2r = p2 + r0 * 66;

    for (int t = 0; t < NT; t++){
        const int cur = t & 1;
        const float* xcn_c = xcn + cur * (C_DIM * TN);
        const float* xnc_c = xnc + cur * (TN * C_DIM);

        // prefetch next tile into registers (overlaps GEMM1)
        if (t + 1 < NT){
            int n0 = (t + 1) * TN;
            #pragma unroll
            for (int p = 0; p < 4; p++){
                int s = tid + NTHREADS * p;
                int cc = s >> 4, g = s & 15;
                pref[p] = *(const float4*)(xb + (size_t)cc * HW_DIM + n0 + 4 * g);
            }
        }

        // GEMM1: S[3][4] = q[3rows] . xtile  (k over C=64)
        u64 s2[3][2];
        #pragma unroll
        for (int i = 0; i < 3; i++){ s2[i][0] = 0ULL; s2[i][1] = 0ULL; }
        #pragma unroll 16
        for (int k = 0; k < C_DIM; k++){
            const u64* xv = (const u64*)(xcn_c + k * TN + c0);
            u64 xlo = xv[0], xhi = xv[1];
            #pragma unroll
            for (int i = 0; i < 3; i++){
                u64 qd = q2r[i * 66 + k];
                s2[i][0] = ffma2(qd, xlo, s2[i][0]);
                s2[i][1] = ffma2(qd, xhi, s2[i][1]);
            }
        }

        // exp (no max needed: |logit| <~ 2), rowsum, stage duplicated P pairs
        #pragma unroll
        for (int i = 0; i < 3; i++){
            float2 a  = unpack2(s2[i][0]);
            float2 bb = unpack2(s2[i][1]);
            float e0 = __expf(a.x),  e1 = __expf(a.y);
            float e2 = __expf(bb.x), e3 = __expf(bb.y);
            rsum[i] = fadd2(rsum[i], pack2(e0 + e2, e1 + e3));
            u64* dst = p2r + i * 66 + c0;
            ulonglong2 st0; st0.x = pack2(e0, e0); st0.y = pack2(e1, e1);
            ulonglong2 st1; st1.x = pack2(e2, e2); st1.y = pack2(e3, e3);
            *(ulonglong2*)(dst)     = st0;
            *(ulonglong2*)(dst + 2) = st1;
        }
        __syncthreads();             // P visible to all before GEMM2

        if (t + 1 < NT) store_tile((t + 1) & 1);

        // GEMM2: O[3][4cols of C] += P[3rows] . x^T  (k over n=64)
        #pragma unroll 16
        for (int n = 0; n < TN; n++){
            const u64* xv = (const u64*)(xnc_c + n * 64 + (c0 ^ ((n & 15) << 2)));
            u64 xlo = xv[0], xhi = xv[1];
            #pragma unroll
            for (int i = 0; i < 3; i++){
                u64 pd = p2r[i * 66 + n];
                oacc[i][0] = ffma2(pd, xlo, oacc[i][0]);
                oacc[i][1] = ffma2(pd, xhi, oacc[i][1]);
            }
        }
        __syncthreads();             // P/xtile fully consumed before next overwrite
    }

    // ---------------- normalize: rowsum reduce over the 16 tx lanes -------------
    float inv[3];
    #pragma unroll
    for (int i = 0; i < 3; i++){
        float2 rr = unpack2(rsum[i]);
        float l = rr.x + rr.y;
        #pragma unroll
        for (int mm = 1; mm <= 8; mm <<= 1)
            l += __shfl_xor_sync(0xffffffffu, l, mm);
        inv[i] = 1.0f / l;
    }

    // ---------------- stage res (transposed to [hc=512][m-pairs]) ---------------
    __syncthreads();
    float* resm = sm;                      // [512][8] overlay (16 KB, q2 dead)
    #pragma unroll
    for (int i = 0; i < 3; i++){
        int r = r0 + i;
        int h = r / 6, m = r - 6 * h;      // out col = h*64 + c, out row = m
        float2 v0 = unpack2(oacc[i][0]);
        float2 v1 = unpack2(oacc[i][1]);
        float vv[4] = {v0.x, v0.y, v1.x, v1.y};
        #pragma unroll
        for (int j2 = 0; j2 < 4; j2++){
            int hc = h * 64 + c0 + j2;
            resm[hc * 8 + m] = vv[j2] * inv[i];
        }
    }
    __syncthreads();

    // ---------------- out = resT @ Wo + bo + z ----------------------------------
    if (tid < D_DIM){
        const int j = tid;
        u64 acc[3] = {0ULL, 0ULL, 0ULL};
        #pragma unroll 8
        for (int k = 0; k < INNER; k++){
            float w = Wo[(size_t)k * D_DIM + j];
            u64 wd = pack2(w, w);
            const u64* rm = (const u64*)(resm + k * 8);
            #pragma unroll
            for (int p = 0; p < 3; p++)
                acc[p] = ffma2(wd, rm[p], acc[p]);
        }
        const float bj = bo[j];
        const float* zb = z   + (size_t)b * M_DIM * D_DIM;
        float*       ob = out + (size_t)b * M_DIM * D_DIM;
        #pragma unroll
        for (int p = 0; p < 3; p++){
            float2 v = unpack2(acc[p]);
            ob[(2 * p)     * D_DIM + j] = v.x + bj + zb[(2 * p)     * D_DIM + j];
            ob[(2 * p + 1) * D_DIM + j] = v.y + bj + zb[(2 * p + 1) * D_DIM + j];
        }
    }
}

extern "C" void kernel_launch(void* const* d_in, const int* in_sizes, int n_in,
                              void* d_out, int out_size)
{
    const float* x  = (const float*)d_in[0];
    const float* z  = (const float*)d_in[1];
    const float* Wq = (const float*)d_in[2];
    const float* bq = (const float*)d_in[3];
    const float* Wo = (const float*)d_in[4];
    const float* bo = (const float*)d_in[5];
    float* out = (float*)d_out;

    // idempotent, not a stream op — safe under graph capture
    cudaFuncSetAttribute(m2f_kernel, cudaFuncAttributeMaxDynamicSharedMemorySize,
                         SMEM_FLOATS * sizeof(float));
    m2f_kernel<<<NB, NTHREADS, SMEM_FLOATS * sizeof(float)>>>(x, z, Wq, bq, Wo, bo, out);
}